// round 1
// baseline (speedup 1.0000x reference)
#include <cuda_runtime.h>

#define G 64
#define S (G*G*G)          // 262144 cells
#define L 64
#define NPTS 150000

// ---------------- scratch (device globals; no allocation allowed) ----------
__device__ float g_sums[S*L];        // 67 MB: scatter sums -> normalized grid
__device__ float g_cnt[S];           // 1 MB
__device__ float g_mid[S*L];         // 67 MB: conv1 output
__device__ float g_wp1[27*L*L];      // conv1 weights repacked [tap][i][o]
__device__ float g_wp2[27*L*L];

// ---------------- weight repack: (O,I,3,3,3) -> [t][i][o] -------------------
__global__ void repack_w(const float* __restrict__ cw, float* __restrict__ dst) {
    int idx = blockIdx.x * 256 + threadIdx.x;
    if (idx < 27*64*64) {
        int t = idx >> 12;          // tap
        int r = idx & 4095;
        int i = r >> 6, o = r & 63;
        dst[idx] = cw[(o*64 + i)*27 + t];
    }
}

// ---------------- fused point MLP + atomic scatter --------------------------
__global__ __launch_bounds__(256) void mlp_scatter(
    const float* __restrict__ pos, const int* __restrict__ pts,
    const float* __restrict__ W1, const float* __restrict__ b1,
    const float* __restrict__ W2, const float* __restrict__ b2,
    const float* __restrict__ Wk1, const float* __restrict__ bk1,
    const float* __restrict__ Wk2, const float* __restrict__ bk2)
{
    __shared__ float W2s[64*64];
    __shared__ float W1s[192], b1s[64], b2s[64], Wk1s[64], bk1s[8], Wk2s[8], bk2s[1];
    __shared__ __align__(16) float h_s[4][512];   // 4 point-groups x (8k x 64l)
    __shared__ float pos_s[4][24];
    __shared__ int   cell_s[4];

    int tid = threadIdx.x;
    for (int i = tid; i < 4096; i += 256) W2s[i] = W2[i];
    if (tid < 192) W1s[tid] = W1[tid];
    if (tid < 64) { b1s[tid] = b1[tid]; b2s[tid] = b2[tid]; Wk1s[tid] = Wk1[tid]; }
    if (tid < 8)  { bk1s[tid] = bk1[tid]; Wk2s[tid] = Wk2[tid]; }
    if (tid == 0) bk2s[0] = bk2[0];
    __syncthreads();

    int grp = tid >> 6, l = tid & 63;
    for (int base = blockIdx.x * 4; base < NPTS; base += gridDim.x * 4) {
        int p = base + grp;
        bool valid = p < NPTS;
        if (valid && l < 24) pos_s[grp][l] = pos[p*24 + l];
        if (valid && l == 0)
            cell_s[grp] = (pts[p*3]*G + pts[p*3+1])*G + pts[p*3+2];
        __syncthreads();

        // h[k][l] = lrelu(pos . W1 + b1)
        #pragma unroll
        for (int k = 0; k < 8; ++k) {
            float v = pos_s[grp][k*3+0]*W1s[l] + pos_s[grp][k*3+1]*W1s[64+l]
                    + pos_s[grp][k*3+2]*W1s[128+l] + b1s[l];
            h_s[grp][k*64 + l] = v >= 0.f ? v : 0.01f*v;
        }
        __syncthreads();

        // feat[k][l] = h[k] @ W2 + b2   (no activation)
        float acc[8];
        #pragma unroll
        for (int k = 0; k < 8; ++k) acc[k] = b2s[l];
        #pragma unroll 4
        for (int j = 0; j < 64; j += 4) {
            float w0 = W2s[(j+0)*64+l], w1 = W2s[(j+1)*64+l];
            float w2 = W2s[(j+2)*64+l], w3 = W2s[(j+3)*64+l];
            #pragma unroll
            for (int k = 0; k < 8; ++k) {
                float4 hv = *(const float4*)&h_s[grp][k*64 + j];
                acc[k] += hv.x*w0 + hv.y*w1 + hv.z*w2 + hv.w*w3;
            }
        }

        // f1 = lrelu(Wk1 @ feat + bk1); f2 = Wk2 @ f1 + bk2
        float f1[8];
        #pragma unroll
        for (int o = 0; o < 8; ++o) {
            float s = bk1s[o];
            #pragma unroll
            for (int k = 0; k < 8; ++k) s += Wk1s[o*8 + k] * acc[k];
            f1[o] = s >= 0.f ? s : 0.01f*s;
        }
        float f2 = bk2s[0];
        #pragma unroll
        for (int o = 0; o < 8; ++o) f2 += Wk2s[o] * f1[o];

        if (valid) {
            int cell = cell_s[grp];
            atomicAdd(&g_sums[cell*64 + l], f2);
            if (l == 0) atomicAdd(&g_cnt[cell], 1.0f);
        }
        __syncthreads();
    }
}

// ---------------- normalize: grid = sums / max(cnt,1), 0 where empty --------
__global__ void normalize_k() {
    int idx = blockIdx.x * 256 + threadIdx.x;   // over 4,194,304 float4s
    float c = g_cnt[idx >> 4];                  // 16 float4 per cell
    float inv = c > 0.f ? 1.f / c : 0.f;
    float4 v = ((float4*)g_sums)[idx];
    v.x *= inv; v.y *= inv; v.z *= inv; v.w *= inv;
    ((float4*)g_sums)[idx] = v;
}

// ---------------- conv3d 64->64ch, 3x3x3, pad 1, + bias, ReLU ---------------
// block = one (d,h) row (64 w) x 64 out-channels; 128 threads, 8x4 reg tile.
__global__ __launch_bounds__(128) void conv3d_k(
    const float* __restrict__ x, float* __restrict__ y,
    const float* __restrict__ wt /* [27][64i][64o] */,
    const float* __restrict__ bias)
{
    __shared__ __align__(16) float As[64*67];   // [i][w+1], stride 67 (conflict-free)
    __shared__ __align__(16) float Bs[64*64];   // [i][o] for current tap
    int tid = threadIdx.x;
    int bh = blockIdx.x & 63, bd = blockIdx.x >> 6;
    int to = tid & 15;    // o tile: o = to*4 .. to*4+3
    int tw = tid >> 4;    // w tile: w = tw*8 .. tw*8+7

    float4 acc[8];
    #pragma unroll
    for (int m = 0; m < 8; ++m) acc[m] = make_float4(0.f, 0.f, 0.f, 0.f);

    for (int dzy = 0; dzy < 9; ++dzy) {
        int dd = bd + dzy/3 - 1;
        int hh = bh + dzy%3 - 1;
        if ((unsigned)dd >= (unsigned)G || (unsigned)hh >= (unsigned)G) continue;
        const float* xrow = x + (size_t)((dd*G + hh)*G) * 64;

        __syncthreads();   // prior GEMM done before overwriting As
        // transpose-load row: As[i][w+1] = xrow[w][i]; vectorized over i
        for (int idx4 = tid; idx4 < 1024; idx4 += 128) {
            int w = idx4 >> 4, i0 = (idx4 & 15) * 4;
            float4 v = ((const float4*)xrow)[idx4];
            As[(i0+0)*67 + w + 1] = v.x;
            As[(i0+1)*67 + w + 1] = v.y;
            As[(i0+2)*67 + w + 1] = v.z;
            As[(i0+3)*67 + w + 1] = v.w;
        }
        if (tid < 64) { As[tid*67] = 0.f; As[tid*67 + 65] = 0.f; }  // w padding

        for (int dx = 0; dx < 3; ++dx) {
            __syncthreads();   // prior GEMM done before overwriting Bs
            const float4* wsrc = (const float4*)(wt + (dzy*3 + dx)*4096);
            for (int idx4 = tid; idx4 < 1024; idx4 += 128)
                ((float4*)Bs)[idx4] = wsrc[idx4];
            __syncthreads();

            int abase = tw*8 + dx;   // As index = i*67 + (w + dx)
            #pragma unroll 4
            for (int i = 0; i < 64; ++i) {
                float4 bv = *(const float4*)&Bs[i*64 + to*4];
                #pragma unroll
                for (int m = 0; m < 8; ++m) {
                    float a = As[i*67 + abase + m];
                    acc[m].x += a * bv.x;
                    acc[m].y += a * bv.y;
                    acc[m].z += a * bv.z;
                    acc[m].w += a * bv.w;
                }
            }
        }
    }

    float4 bb = *(const float4*)&bias[to*4];
    int sbase = (bd*G + bh)*G;
    #pragma unroll
    for (int m = 0; m < 8; ++m) {
        int w = tw*8 + m;
        float4 r;
        r.x = fmaxf(acc[m].x + bb.x, 0.f);
        r.y = fmaxf(acc[m].y + bb.y, 0.f);
        r.z = fmaxf(acc[m].z + bb.z, 0.f);
        r.w = fmaxf(acc[m].w + bb.w, 0.f);
        *(float4*)&y[(size_t)(sbase + w)*64 + to*4] = r;
    }
}

// ---------------- launch -----------------------------------------------------
extern "C" void kernel_launch(void* const* d_in, const int* in_sizes, int n_in,
                              void* d_out, int out_size)
{
    const float* pos = (const float*)d_in[0];
    const int*   pts = (const int*)d_in[1];
    const float* W1  = (const float*)d_in[2];
    const float* b1  = (const float*)d_in[3];
    const float* W2  = (const float*)d_in[4];
    const float* b2  = (const float*)d_in[5];
    const float* Wk1 = (const float*)d_in[6];
    const float* bk1 = (const float*)d_in[7];
    const float* Wk2 = (const float*)d_in[8];
    const float* bk2 = (const float*)d_in[9];
    const float* Cw1 = (const float*)d_in[10];
    const float* Cb1 = (const float*)d_in[11];
    const float* Cw2 = (const float*)d_in[12];
    const float* Cb2 = (const float*)d_in[13];
    float* out = (float*)d_out;

    void *pSums, *pCnt, *pMid, *pW1, *pW2;
    cudaGetSymbolAddress(&pSums, g_sums);
    cudaGetSymbolAddress(&pCnt,  g_cnt);
    cudaGetSymbolAddress(&pMid,  g_mid);
    cudaGetSymbolAddress(&pW1,   g_wp1);
    cudaGetSymbolAddress(&pW2,   g_wp2);

    cudaMemsetAsync(pSums, 0, sizeof(float) * (size_t)S * L);
    cudaMemsetAsync(pCnt,  0, sizeof(float) * (size_t)S);

    repack_w<<<432, 256>>>(Cw1, (float*)pW1);
    repack_w<<<432, 256>>>(Cw2, (float*)pW2);

    mlp_scatter<<<2368, 256>>>(pos, pts, W1, b1, W2, b2, Wk1, bk1, Wk2, bk2);
    normalize_k<<<16384, 256>>>();

    conv3d_k<<<G*G, 128>>>((const float*)pSums, (float*)pMid, (const float*)pW1, Cb1);
    conv3d_k<<<G*G, 128>>>((const float*)pMid,  out,          (const float*)pW2, Cb2);
}